// round 6
// baseline (speedup 1.0000x reference)
#include <cuda_runtime.h>
#include <cstdint>

#define NM    100          // num instances (dataset constant)
#define NPAD  101          // padded bins per lane (odd stride -> conflict-free LDS.64)
#define WARPS 8
#define BLK   (WARPS*32)
#define TP    16           // points per register tile
#define KCH   91           // chunks per warp-row (13 wr * 91 = 1183 tasks = 148*8-1 warps)
#define WR    13           // warp-rows: ceil(400/32)
#define NTASK (WR*KCH)
#define NSEG  7            // reduce stage-1 segments (7*13 = 91)
#define KSEG  13
#define HBLK  148          // hist blocks

#define ACC_BYTES (BLK*NPAD*sizeof(float2))   /* 206848 B -> 1 block/SM, 8 warps */

// fp32 partials per task: [task][j][lane] float2, plus per-lane row-sum of B
__device__ float2 g_acc[(size_t)NTASK * NM * 32];   // ~30.3 MB
__device__ float  g_sc [(size_t)NTASK * 32];
__device__ int    g_hist[HBLK * NM];
__device__ int    g_counts[NM];
// stage-1 reduce partials
__device__ float2 g_part [(size_t)NSEG * NM * WR * 32];  // ~2.33 MB
__device__ float  g_spart[(size_t)NSEG * WR * 32];

// per-block histogram, no global atomics (summed later in reduce1)
__global__ void hist_kernel(const int* __restrict__ labels, int P) {
    __shared__ int sb[NM];
    for (int i = threadIdx.x; i < NM; i += blockDim.x) sb[i] = 0;
    __syncthreads();
    for (int i = blockIdx.x * blockDim.x + threadIdx.x; i < P;
         i += gridDim.x * blockDim.x) {
        int l = labels[i];
        if ((unsigned)l < (unsigned)NM) atomicAdd(&sb[l], 1);
    }
    __syncthreads();
    for (int i = threadIdx.x; i < NM; i += blockDim.x)
        g_hist[blockIdx.x * NM + i] = sb[i];
}

// per-point math: EX2 + RCP + LG2 MUFU, ~25 issue slots total.
// A = (1-s)^2 * (-log s), B = s^2 * (-log(1-s));  f1-f0 = 0.25*(A-3B), f0 = 0.75*B
__device__ __forceinline__ void point_math(float x, float& d, float& B, float& s)
{
    const float t  = __expf(-fabsf(x));
    const float dn = 1.0f + t;
    const float r  = __fdividef(1.0f, dn);
    const float tr = t * r;
    const float L  = __logf(dn);              // log(1+e^-|x|)
    const bool pos = (x >= 0.0f);
    s = pos ? r  : tr;                        // sigmoid(x)
    const float o  = pos ? tr : r;            // 1 - sigmoid(x)
    const float t1 = L - fminf(x, 0.0f);      // -log_sigmoid(x)
    const float t2 = L + fmaxf(x, 0.0f);      // -log_sigmoid(-x)
    const float A  = (o * o) * t1;
    B = (s * s) * t2;
    d = fmaf(-3.0f, B, A);
}

__global__ __launch_bounds__(BLK, 1)
void main_kernel(const float* __restrict__ pred, const int* __restrict__ labels,
                 int Q, int P, int pc) {
    extern __shared__ float2 acc[];

    const int tid  = threadIdx.x;
    const int w    = tid >> 5;
    const int lane = tid & 31;

    float2* myacc = acc + tid * NPAD;
    #pragma unroll 4
    for (int j = 0; j < NPAD; ++j) myacc[j] = make_float2(0.f, 0.f);

    const int g = w * gridDim.x + blockIdx.x;    // per-SM balanced task map
    if (g >= NTASK) return;
    const int wr = g / KCH;
    const int k  = g - wr * KCH;

    const int q  = wr * 32 + lane;
    const int qc = (q < Q) ? q : (Q - 1);        // clamp; invalid lanes harmless
    const float* __restrict__ rowp = pred + (size_t)qc * P;

    const int pstart = k * pc;
    const int pend   = (pstart + pc < P) ? (pstart + pc) : P;

    float sumB = 0.f;

    if (pstart < pend) {
        const int npts  = pend - pstart;
        const int nfull = npts >> 4;
        const int ntail = npts & 15;

        float4 b0, b1, b2, b3;
        int labv;
        {
            const float* rp = rowp + pstart;
            b0 = *reinterpret_cast<const float4*>(rp + 0);
            b1 = *reinterpret_cast<const float4*>(rp + 4);
            b2 = *reinterpret_cast<const float4*>(rp + 8);
            b3 = *reinterpret_cast<const float4*>(rp + 12);
            labv = labels[pstart + (lane & 15)];
        }

        int pt0 = pstart;
        for (int tile = 0; tile < nfull; ++tile, pt0 += TP) {
            float c[TP];
            c[0]=b0.x; c[1]=b0.y; c[2]=b0.z; c[3]=b0.w;
            c[4]=b1.x; c[5]=b1.y; c[6]=b1.z; c[7]=b1.w;
            c[8]=b2.x; c[9]=b2.y; c[10]=b2.z; c[11]=b2.w;
            c[12]=b3.x; c[13]=b3.y; c[14]=b3.z; c[15]=b3.w;
            const int lv = labv;

            const int nxt = pt0 + TP;
            if (nxt + TP <= pend) {              // prefetch next full tile
                const float* rp = rowp + nxt;
                b0 = *reinterpret_cast<const float4*>(rp + 0);
                b1 = *reinterpret_cast<const float4*>(rp + 4);
                b2 = *reinterpret_cast<const float4*>(rp + 8);
                b3 = *reinterpret_cast<const float4*>(rp + 12);
                labv = labels[nxt + (lane & 15)];
            }

            #pragma unroll
            for (int i = 0; i < TP; ++i) {
                const int lab = __shfl_sync(0xffffffffu, lv, i);
                float d, B, s;
                point_math(c[i], d, B, s);
                float2 a = myacc[lab];            // conflict-free, lane-private
                a.x += d;
                a.y += s;
                myacc[lab] = a;
                sumB += B;
            }
        }

        if (ntail) {                              // generic tail (unused for P=200000)
            #pragma unroll
            for (int i = 0; i < TP; ++i) {
                if (i < ntail) {
                    const int lab = labels[pt0 + i];
                    float d, B, s;
                    point_math(rowp[pt0 + i], d, B, s);
                    float2 a = myacc[lab];
                    a.x += d; a.y += s;
                    myacc[lab] = a;
                    sumB += B;
                }
            }
        }
    }

    float2* dst = g_acc + (size_t)g * NM * 32;
    #pragma unroll 4
    for (int j = 0; j < NM; ++j) dst[j * 32 + lane] = myacc[j];
    g_sc[(size_t)g * 32 + lane] = sumB;
}

// stage 1: grid (NM/8, WR, NSEG), block (32,8)
__global__ void reduce1_kernel() {
    const int lane = threadIdx.x;
    const int ty   = threadIdx.y;
    const int j    = blockIdx.x * 8 + ty;
    const int wr   = blockIdx.y;
    const int seg  = blockIdx.z;

    if (j < NM) {
        float s1 = 0.f, s2 = 0.f;
        const size_t base = (size_t)wr * KCH + seg * KSEG;
        #pragma unroll
        for (int k = 0; k < KSEG; ++k) {
            float2 a = g_acc[((base + k) * NM + j) * 32 + lane];
            s1 += a.x; s2 += a.y;
        }
        g_part[(((size_t)seg * NM + j) * WR + wr) * 32 + lane] = make_float2(s1, s2);
    }

    if (ty == 0 && blockIdx.x == 0) {        // row-sum-of-B partials
        float sf = 0.f;
        const size_t base = (size_t)wr * KCH + seg * KSEG;
        #pragma unroll
        for (int k = 0; k < KSEG; ++k) sf += g_sc[(base + k) * 32 + lane];
        g_spart[((size_t)seg * WR + wr) * 32 + lane] = sf;
    }

    if (seg == 0 && wr == 0 && j < NM) {     // fold per-block histograms -> counts
        int c = 0;
        for (int b = lane; b < HBLK; b += 32) c += g_hist[b * NM + j];
        #pragma unroll
        for (int o = 16; o > 0; o >>= 1) c += __shfl_xor_sync(0xffffffffu, c, o);
        if (lane == 0) g_counts[j] = c;
    }
}

// stage 2: grid (WR), block (32,8): each block finalizes 32 queries x all 100 j
__global__ void reduce2_kernel(float* __restrict__ out, int Q, float invP) {
    __shared__ float spbuf[8][33];
    const int lane = threadIdx.x;
    const int ty   = threadIdx.y;
    const int wr   = blockIdx.x;
    const int q    = wr * 32 + lane;

    float s1v[13], s2v[13];
    float sp_part = 0.f;
    #pragma unroll
    for (int m = 0; m < 13; ++m) {
        const int j = ty + 8 * m;
        float s1 = 0.f, s2 = 0.f;
        if (j < NM) {
            #pragma unroll
            for (int seg = 0; seg < NSEG; ++seg) {
                float2 a = g_part[(((size_t)seg * NM + j) * WR + wr) * 32 + lane];
                s1 += a.x; s2 += a.y;
            }
        }
        s1v[m] = s1; s2v[m] = s2;
        sp_part += s2;                        // Sum_p sigmoid = Sum_j bins
    }
    spbuf[ty][lane] = sp_part;
    __syncthreads();
    float sp = 0.f;
    #pragma unroll
    for (int y = 0; y < 8; ++y) sp += spbuf[y][lane];

    float sf = 0.f;                           // Sum_p B for this row
    #pragma unroll
    for (int seg = 0; seg < NSEG; ++seg)
        sf += g_spart[((size_t)seg * WR + wr) * 32 + lane];

    if (q >= Q) return;
    #pragma unroll
    for (int m = 0; m < 13; ++m) {
        const int j = ty + 8 * m;
        if (j < NM) {
            const float cnt = (float)g_counts[j];
            const float cost_mask = (0.25f * s1v[m] + 0.75f * sf) * invP;
            const float cost_dice = 1.0f - (2.0f * s2v[m] + 1.0f) / (sp + cnt + 1.0f);
            out[(size_t)q * NM + j] = cost_mask + cost_dice;
        }
    }
}

extern "C" void kernel_launch(void* const* d_in, const int* in_sizes, int n_in,
                              void* d_out, int out_size) {
    const float* pred   = (const float*)d_in[0];
    const int*   labels = (const int*)d_in[1];

    const int P = in_sizes[1];
    const int Q = in_sizes[0] / P;
    const int pc = (((P + KCH - 1) / KCH) + TP - 1) / TP * TP;

    cudaFuncSetAttribute(main_kernel, cudaFuncAttributeMaxDynamicSharedMemorySize,
                         ACC_BYTES);

    // exactly 4 launches per call -> ncu -s 5 -c 1 captures main_kernel
    hist_kernel<<<HBLK, 256>>>(labels, P);
    main_kernel<<<148, BLK, ACC_BYTES>>>(pred, labels, Q, P, pc);
    reduce1_kernel<<<dim3((NM + 7) / 8, WR, NSEG), dim3(32, 8)>>>();
    reduce2_kernel<<<WR, dim3(32, 8)>>>((float*)d_out, Q, 1.0f / (float)P);
}

// round 7
// speedup vs baseline: 1.0385x; 1.0385x over previous
#include <cuda_runtime.h>
#include <cstdint>

#define NM    100          // num instances (dataset constant)
#define NPAD  101          // padded bins per lane (odd stride -> conflict-free LDS.64)
#define WARPS 8
#define BLK   (WARPS*32)
#define TP    16           // points per register tile
#define KCH   91           // chunks per warp-row (13 wr * 91 = 1183 tasks = 148*8-1 warps)
#define WR    13           // warp-rows: ceil(400/32)
#define NTASK (WR*KCH)
#define NSEG  7            // reduce stage-1 segments (7*13 = 91)
#define KSEG  13
#define HBLK  148          // hist blocks

#define ACC_BYTES (BLK*NPAD*sizeof(float2))   /* 206848 B -> 1 block/SM, 8 warps */

// fp32 partials per task: [task][j][lane] float2, plus per-lane (sumB, sump)
__device__ float2   g_acc[(size_t)NTASK * NM * 32];   // ~30.3 MB
__device__ float2   g_sc [(size_t)NTASK * 32];
__device__ int      g_hist[HBLK * NM];
__device__ int      g_counts[NM];
__device__ uint32_t g_labpack[65536];                  // byte-packed labels (P<=262144)
// stage-1 reduce partials
__device__ float2   g_part [(size_t)NSEG * NM * WR * 32];  // ~2.33 MB
__device__ float2   g_spart[(size_t)NSEG * WR * 32];

// pack labels (ints < 256) into bytes: one u32 per 4 points
__global__ void pack_labels_kernel(const int* __restrict__ labels, int P) {
    const int i = blockIdx.x * blockDim.x + threadIdx.x;
    const int base = i * 4;
    if (base >= P) return;
    uint32_t w = 0;
    if (base + 3 < P) {
        int4 l = *reinterpret_cast<const int4*>(labels + base);
        w = (uint32_t)(l.x & 0xFF) | ((uint32_t)(l.y & 0xFF) << 8) |
            ((uint32_t)(l.z & 0xFF) << 16) | ((uint32_t)(l.w & 0xFF) << 24);
    } else {
        for (int k = 0; k < 4 && base + k < P; ++k)
            w |= (uint32_t)(labels[base + k] & 0xFF) << (8 * k);
    }
    g_labpack[i] = w;
}

// per-block histogram, no global atomics (summed later in reduce1)
__global__ void hist_kernel(const int* __restrict__ labels, int P) {
    __shared__ int sb[NM];
    for (int i = threadIdx.x; i < NM; i += blockDim.x) sb[i] = 0;
    __syncthreads();
    for (int i = blockIdx.x * blockDim.x + threadIdx.x; i < P;
         i += gridDim.x * blockDim.x) {
        int l = labels[i];
        if ((unsigned)l < (unsigned)NM) atomicAdd(&sb[l], 1);
    }
    __syncthreads();
    for (int i = threadIdx.x; i < NM; i += blockDim.x)
        g_hist[blockIdx.x * NM + i] = sb[i];
}

// per-point math: EX2 + RCP + LG2 MUFU.
// A = (1-s)^2*(-log s), B = s^2*(-log(1-s));  f1-f0 = 0.25*(A-3B), f0 = 0.75*B
__device__ __forceinline__ void point_math(float x, float& d, float& B, float& s)
{
    const float t  = __expf(-fabsf(x));
    const float dn = 1.0f + t;
    const float r  = __fdividef(1.0f, dn);
    const float tr = t * r;
    const float L  = __logf(dn);              // log(1+e^-|x|)
    const bool pos = (x >= 0.0f);
    s = pos ? r  : tr;                        // sigmoid(x)
    const float o  = pos ? tr : r;            // 1 - sigmoid(x)
    const float t1 = L - fminf(x, 0.0f);      // -log_sigmoid(x)
    const float t2 = L + fmaxf(x, 0.0f);      // -log_sigmoid(-x)
    const float A  = (o * o) * t1;
    B = (s * s) * t2;
    d = fmaf(-3.0f, B, A);
}

__global__ __launch_bounds__(BLK, 1)
void main_kernel(const float* __restrict__ pred, const int* __restrict__ labels,
                 int Q, int P, int pc) {
    extern __shared__ float2 acc[];

    const int tid  = threadIdx.x;
    const int w    = tid >> 5;
    const int lane = tid & 31;

    float2* myacc = acc + tid * NPAD;
    #pragma unroll 4
    for (int j = 0; j < NPAD; ++j) myacc[j] = make_float2(0.f, 0.f);

    const int g = w * gridDim.x + blockIdx.x;    // per-SM balanced task map
    if (g >= NTASK) return;
    const int wr = g / KCH;
    const int k  = g - wr * KCH;

    const int q  = wr * 32 + lane;
    const int qc = (q < Q) ? q : (Q - 1);        // clamp; invalid lanes harmless
    const float* __restrict__ rowp = pred + (size_t)qc * P;

    const int pstart = k * pc;
    const int pend   = (pstart + pc < P) ? (pstart + pc) : P;

    float sumB = 0.f, sump = 0.f;

    if (pstart < pend) {
        const int npts  = pend - pstart;
        const int nfull = npts >> 4;
        const int ntail = npts & 15;

        float4 b0, b1, b2, b3;
        uint4  lw;                               // 16 packed labels (uniform)
        {
            const float* rp = rowp + pstart;
            b0 = *reinterpret_cast<const float4*>(rp + 0);
            b1 = *reinterpret_cast<const float4*>(rp + 4);
            b2 = *reinterpret_cast<const float4*>(rp + 8);
            b3 = *reinterpret_cast<const float4*>(rp + 12);
            lw = *reinterpret_cast<const uint4*>(g_labpack + (pstart >> 2));
        }

        int pt0 = pstart;
        for (int tile = 0; tile < nfull; ++tile, pt0 += TP) {
            float c[TP];
            c[0]=b0.x; c[1]=b0.y; c[2]=b0.z; c[3]=b0.w;
            c[4]=b1.x; c[5]=b1.y; c[6]=b1.z; c[7]=b1.w;
            c[8]=b2.x; c[9]=b2.y; c[10]=b2.z; c[11]=b2.w;
            c[12]=b3.x; c[13]=b3.y; c[14]=b3.z; c[15]=b3.w;
            uint32_t lv[4] = {lw.x, lw.y, lw.z, lw.w};

            const int nxt = pt0 + TP;
            if (nxt + TP <= pend) {              // prefetch next full tile
                const float* rp = rowp + nxt;
                b0 = *reinterpret_cast<const float4*>(rp + 0);
                b1 = *reinterpret_cast<const float4*>(rp + 4);
                b2 = *reinterpret_cast<const float4*>(rp + 8);
                b3 = *reinterpret_cast<const float4*>(rp + 12);
                lw = *reinterpret_cast<const uint4*>(g_labpack + (nxt >> 2));
            }

            #pragma unroll
            for (int i = 0; i < TP; ++i) {
                const int lab = __byte_perm(lv[i >> 2], 0, 0x4440u + (i & 3));
                float d, B, s;
                point_math(c[i], d, B, s);
                float2 a = myacc[lab];            // conflict-free, lane-private
                a.x += d;
                a.y += s;
                myacc[lab] = a;
                sumB += B;
                sump += s;
            }
        }

        if (ntail) {                              // generic tail (unused for P=200000)
            #pragma unroll
            for (int i = 0; i < TP; ++i) {
                if (i < ntail) {
                    const int lab = labels[pt0 + i];
                    float d, B, s;
                    point_math(rowp[pt0 + i], d, B, s);
                    float2 a = myacc[lab];
                    a.x += d; a.y += s;
                    myacc[lab] = a;
                    sumB += B; sump += s;
                }
            }
        }
    }

    float2* dst = g_acc + (size_t)g * NM * 32;
    #pragma unroll 4
    for (int j = 0; j < NM; ++j) dst[j * 32 + lane] = myacc[j];
    g_sc[(size_t)g * 32 + lane] = make_float2(sumB, sump);
}

// stage 1: grid (NM/8, WR, NSEG), block (32,8)
__global__ void reduce1_kernel() {
    const int lane = threadIdx.x;
    const int ty   = threadIdx.y;
    const int j    = blockIdx.x * 8 + ty;
    const int wr   = blockIdx.y;
    const int seg  = blockIdx.z;

    if (j < NM) {
        float s1 = 0.f, s2 = 0.f;
        const size_t base = (size_t)wr * KCH + seg * KSEG;
        #pragma unroll
        for (int k = 0; k < KSEG; ++k) {
            float2 a = g_acc[((base + k) * NM + j) * 32 + lane];
            s1 += a.x; s2 += a.y;
        }
        g_part[(((size_t)seg * NM + j) * WR + wr) * 32 + lane] = make_float2(s1, s2);
    }

    if (ty == 0 && blockIdx.x == 0) {        // row scalars (sumB, sump)
        float sf = 0.f, sp = 0.f;
        const size_t base = (size_t)wr * KCH + seg * KSEG;
        #pragma unroll
        for (int k = 0; k < KSEG; ++k) {
            float2 s = g_sc[(base + k) * 32 + lane];
            sf += s.x; sp += s.y;
        }
        g_spart[((size_t)seg * WR + wr) * 32 + lane] = make_float2(sf, sp);
    }

    if (seg == 0 && wr == 0 && j < NM) {     // fold per-block histograms -> counts
        int c = 0;
        for (int b = lane; b < HBLK; b += 32) c += g_hist[b * NM + j];
        #pragma unroll
        for (int o = 16; o > 0; o >>= 1) c += __shfl_xor_sync(0xffffffffu, c, o);
        if (lane == 0) g_counts[j] = c;
    }
}

// stage 2: grid (NM/8, WR), block (32,8): finalize
__global__ void reduce2_kernel(float* __restrict__ out, int Q, float invP) {
    const int lane = threadIdx.x;
    const int j    = blockIdx.x * 8 + threadIdx.y;
    const int wr   = blockIdx.y;
    const int q    = wr * 32 + lane;
    if (q >= Q || j >= NM) return;

    float s1 = 0.f, s2 = 0.f, sf = 0.f, sp = 0.f;
    #pragma unroll
    for (int seg = 0; seg < NSEG; ++seg) {
        float2 a = g_part[(((size_t)seg * NM + j) * WR + wr) * 32 + lane];
        float2 s = g_spart[((size_t)seg * WR + wr) * 32 + lane];
        s1 += a.x; s2 += a.y;
        sf += s.x; sp += s.y;
    }
    const float cnt = (float)g_counts[j];
    const float cost_mask = (0.25f * s1 + 0.75f * sf) * invP;
    const float cost_dice = 1.0f - (2.0f * s2 + 1.0f) / (sp + cnt + 1.0f);
    out[(size_t)q * NM + j] = cost_mask + cost_dice;
}

extern "C" void kernel_launch(void* const* d_in, const int* in_sizes, int n_in,
                              void* d_out, int out_size) {
    const float* pred   = (const float*)d_in[0];
    const int*   labels = (const int*)d_in[1];

    const int P = in_sizes[1];
    const int Q = in_sizes[0] / P;
    const int pc = (((P + KCH - 1) / KCH) + TP - 1) / TP * TP;

    cudaFuncSetAttribute(main_kernel, cudaFuncAttributeMaxDynamicSharedMemorySize,
                         ACC_BYTES);

    pack_labels_kernel<<<(P / 4 + 256) / 256 + 1, 256>>>(labels, P);
    hist_kernel<<<HBLK, 256>>>(labels, P);
    main_kernel<<<148, BLK, ACC_BYTES>>>(pred, labels, Q, P, pc);
    reduce1_kernel<<<dim3((NM + 7) / 8, WR, NSEG), dim3(32, 8)>>>();
    reduce2_kernel<<<dim3((NM + 7) / 8, WR), dim3(32, 8)>>>((float*)d_out, Q,
                                                            1.0f / (float)P);
}